// round 12
// baseline (speedup 1.0000x reference)
#include <cuda_runtime.h>
#include <stdint.h>
#include <math.h>

// Problem constants (fixed by the dataset).
#define NN      8192
#define CC      64
#define EMAX    262144
#define PAD     128                 // padded CSR row stride (mean deg 32)
#define TS      (1u << 19)          // hash slots (load factor ~0.5)
#define TMASK   (TS - 1u)
#define LISTCAP 16384

// ---------------- scratch (static device globals; no allocation) -------------
__device__ __align__(16) unsigned long long g_table[TS];   // 4 MB dedupe hash
__device__ int      g_is64;
__device__ int      g_count[NN];          // distinct cells per row
__device__ float    g_deg[NN];
__device__ unsigned g_pos[TS];            // apos recorded by the claimant of a slot
__device__ __align__(16) uint2 g_cw[NN * PAD];   // 8 MB interleaved (col, w)
__device__ float2   g_tx1[NN * 32];
__device__ int      g_nlist;
__device__ uint2    g_list[LISTCAP];      // (slot, edge idx) of duplicate-key inserts

// ---------------- kernels ----------------------------------------------------

// Clear table (16B stores) + counters; detect int32 vs int64 edge storage.
__global__ void k_clear(const unsigned* __restrict__ ei) {
    unsigned i = blockIdx.x * blockDim.x + threadIdx.x;       // 262144 threads
    ((ulonglong2*)g_table)[i] = make_ulonglong2(0ull, 0ull);  // 2 slots each
    if (i < NN) { g_count[i] = 0; g_deg[i] = 0.f; }
    if (i == 0) {
        g_nlist = 0;
        int all_zero = 1;
        for (int j = 1; j < 64; j += 2) all_zero &= (ei[j] == 0u);
        g_is64 = all_zero;   // int64 LE with values<2^31 => odd words zero
    }
}

// Insert: claimant of a cell takes a padded-CSR position and writes (col,w) +
// REDG degree. Duplicate-key edges go to a tiny fix list. atomicMax on
// (key+1)<<32|(i+1) keeps the highest edge idx = last-write-wins.
__global__ void k_insert(const unsigned* __restrict__ ei,
                         const float* __restrict__ ew,
                         const float* __restrict__ adw, int E) {
    int i = blockIdx.x * blockDim.x + threadIdx.x;
    if (i >= E) return;
    unsigned row, col;
    if (g_is64) {                                 // coalesced 8B loads
        row = ((const uint2*)ei)[i].x;
        col = ((const uint2*)ei)[E + i].x;
    } else {
        row = ei[i];
        col = ei[E + i];
    }
    float sig = 1.f / (1.f + expf(-adw[0]));
    float aw  = ew[i] * sig;
    unsigned key = (row << 13) | col;                         // < 2^26
    unsigned long long packed =
        ((unsigned long long)(key + 1u) << 32) | (unsigned)(i + 1);
    unsigned slot = ((key * 2654435761u) >> 12) & TMASK;
    while (true) {
        unsigned long long cur = g_table[slot];
        if (cur == 0ull) {
            unsigned long long old = atomicCAS(&g_table[slot], 0ull, packed);
            if (old == 0ull) {                                 // claimed this cell
                int pos = atomicAdd(&g_count[row], 1);
                if (pos < PAD) {
                    unsigned apos = (row << 7) + (unsigned)pos;
                    g_pos[slot] = apos;
                    g_cw[apos]  = make_uint2(col, __float_as_uint(aw));
                    atomicAdd(&g_deg[row], aw);                // REDG (no return)
                }
                return;
            }
            cur = old;
        }
        if ((cur >> 32) == (unsigned long long)(key + 1u)) {   // duplicate cell
            atomicMax(&g_table[slot], packed);
            int p = atomicAdd(&g_nlist, 1);
            if (p < LISTCAP) g_list[p] = make_uint2(slot, (unsigned)i);
            return;
        }
        slot = (slot + 1u) & TMASK;
    }
}

// Apply last-write-wins corrections for duplicate cells (few hundred entries).
__global__ void k_fix(const float* __restrict__ ew,
                      const float* __restrict__ adw) {
    int idx = blockIdx.x * blockDim.x + threadIdx.x;
    int n = g_nlist; if (n > LISTCAP) n = LISTCAP;
    if (idx >= n) return;
    unsigned slot = g_list[idx].x;
    unsigned i    = g_list[idx].y;
    unsigned long long cur = g_table[slot];
    if ((unsigned)cur != i + 1u) return;                       // not the winner
    unsigned apos = g_pos[slot];
    float sig = 1.f / (1.f + expf(-adw[0]));
    float aw  = ew[i] * sig;
    float old = __uint_as_float(g_cw[apos].y);
    g_cw[apos].y = __float_as_uint(aw);
    atomicAdd(&g_deg[apos >> 7], aw - old);
}

// Shared SpMM core: warp per row, edge-exact count, smem-staged edge list,
// LDS.64 broadcast. 2-edge pairs with unroll 4 -> 8 outstanding gathers,
// dual accumulator pairs to break the FMA chain.
// SCALE (spmm1): dinv[col] folded during staging; written back for spmm2.
template <bool SCALE>
__device__ __forceinline__ void spmm_gather(const float2* __restrict__ X2,
                                            uint2* __restrict__ srow,
                                            int gw, int lane,
                                            float& axo, float& ayo) {
    int cnt = g_count[gw]; if (cnt > PAD) cnt = PAD;
    int base = gw << 7;
    for (int j = lane; j < cnt; j += 32) {                     // coalesced stage
        uint2 cw = g_cw[base + j];
        if (SCALE) {
            float w = __uint_as_float(cw.y) * rsqrtf(g_deg[cw.x] + 1.0f);
            cw.y = __float_as_uint(w);
            g_cw[base + j] = cw;                               // persist for spmm2
        }
        srow[j] = cw;
    }
    __syncwarp();

    float ax0 = 0.f, ay0 = 0.f, ax1 = 0.f, ay1 = 0.f;
    int t = 0;
#pragma unroll 4
    for (; t + 1 < cnt; t += 2) {                              // 2 edges/iter
        uint2 e0 = srow[t];                                    // LDS.64 broadcast
        uint2 e1 = srow[t + 1];
        float w0 = __uint_as_float(e0.y);
        float w1 = __uint_as_float(e1.y);
        float2 v0 = X2[e0.x * 32 + lane];
        float2 v1 = X2[e1.x * 32 + lane];
        ax0 = fmaf(w0, v0.x, ax0);  ay0 = fmaf(w0, v0.y, ay0);
        ax1 = fmaf(w1, v1.x, ax1);  ay1 = fmaf(w1, v1.y, ay1);
    }
    if (t < cnt) {
        uint2 e = srow[t];
        float w = __uint_as_float(e.y);
        float2 xv = X2[e.x * 32 + lane];
        ax0 = fmaf(w, xv.x, ax0);  ay0 = fmaf(w, xv.y, ay0);
    }
    axo = ax0 + ax1;
    ayo = ay0 + ay1;
}

__global__ void k_spmm1(const float2* __restrict__ X2) {       // g_tx1 = L x
    __shared__ uint2 s_edges[8][PAD];                          // 8 KB
    int gw = (blockIdx.x * blockDim.x + threadIdx.x) >> 5;
    if (gw >= NN) return;
    int lane = threadIdx.x & 31;
    float ax, ay;
    spmm_gather<true>(X2, s_edges[(threadIdx.x >> 5) & 7], gw, lane, ax, ay);
    float di = rsqrtf(g_deg[gw] + 1.0f);
    float2 xs = X2[gw * 32 + lane];
    g_tx1[gw * 32 + lane] = make_float2(xs.x - di * (ax + di * xs.x),
                                        xs.y - di * (ay + di * xs.y));
}

// spmm2 fused with the epilogue: compute LTx1 row in registers, then directly
// out[row] = x*W0 + Tx1*W1 + (2*LTx1 - x)*W2 + bias. W read via uniform LDG
// (48 KB, L1-resident) -> no extra smem, occupancy preserved. Kills k_out and
// the g_ltx1 buffer round-trip.
__global__ void k_spmm2_out(const float2* __restrict__ X2,
                            const float* __restrict__ W,
                            const float* __restrict__ bias,
                            float2* __restrict__ O2) {
    __shared__ uint2 s_edges[8][PAD];                          // 8 KB
    int gw = (blockIdx.x * blockDim.x + threadIdx.x) >> 5;
    if (gw >= NN) return;
    int lane = threadIdx.x & 31;
    float ax, ay;
    spmm_gather<false>(g_tx1, s_edges[(threadIdx.x >> 5) & 7], gw, lane, ax, ay);

    float di = rsqrtf(g_deg[gw] + 1.0f);
    float2 t1 = g_tx1[gw * 32 + lane];
    float2 lv;                                                 // LTx1 row
    lv.x = t1.x - di * (ax + di * t1.x);
    lv.y = t1.y - di * (ay + di * t1.y);
    float2 xv = X2[gw * 32 + lane];
    float2 t2;                                                 // Tx2 row
    t2.x = 2.f * lv.x - xv.x;
    t2.y = 2.f * lv.y - xv.y;

    const float2* __restrict__ W2 = (const float2*)W;
    float accx = 0.f, accy = 0.f;
#pragma unroll 8
    for (int kp = 0; kp < 32; kp++) {
        int k0 = 2 * kp, k1 = 2 * kp + 1;
        float bx0 = __shfl_sync(0xffffffffu, xv.x, kp);
        float bx1 = __shfl_sync(0xffffffffu, xv.y, kp);
        float b10 = __shfl_sync(0xffffffffu, t1.x, kp);
        float b11 = __shfl_sync(0xffffffffu, t1.y, kp);
        float b20 = __shfl_sync(0xffffffffu, t2.x, kp);
        float b21 = __shfl_sync(0xffffffffu, t2.y, kp);
        float2 w00 = W2[k0 * 32 + lane],        w01 = W2[k1 * 32 + lane];
        float2 w10 = W2[2048 + k0 * 32 + lane], w11 = W2[2048 + k1 * 32 + lane];
        float2 w20 = W2[4096 + k0 * 32 + lane], w21 = W2[4096 + k1 * 32 + lane];
        accx = fmaf(bx0, w00.x, accx); accx = fmaf(bx1, w01.x, accx);
        accx = fmaf(b10, w10.x, accx); accx = fmaf(b11, w11.x, accx);
        accx = fmaf(b20, w20.x, accx); accx = fmaf(b21, w21.x, accx);
        accy = fmaf(bx0, w00.y, accy); accy = fmaf(bx1, w01.y, accy);
        accy = fmaf(b10, w10.y, accy); accy = fmaf(b11, w11.y, accy);
        accy = fmaf(b20, w20.y, accy); accy = fmaf(b21, w21.y, accy);
    }
    float2 b2 = ((const float2*)bias)[lane];
    O2[gw * 32 + lane] = make_float2(accx + b2.x, accy + b2.y);
}

// ---------------- launch -----------------------------------------------------

extern "C" void kernel_launch(void* const* d_in, const int* in_sizes, int n_in,
                              void* d_out, int out_size) {
    const float*    x    = (const float*)d_in[0];
    const unsigned* ei   = (const unsigned*)d_in[1];   // int32 OR int64 raw words
    const float*    ew   = (const float*)d_in[2];      // (E,)
    const float*    W    = (const float*)d_in[3];      // (3, 64, 64)
    const float*    adw  = (const float*)d_in[4];      // (1,)
    const float*    bias = (const float*)d_in[5];      // (64,)
    float*          out  = (float*)d_out;

    int E = in_sizes[2];
    if (E > EMAX) E = EMAX;   // fixed problem; defensive only
    int eb = (E + 255) / 256;

    k_clear    <<<TS / 2 / 256, 256>>>(ei);            // 1024 blocks
    k_insert   <<<eb, 256>>>(ei, ew, adw, E);
    k_fix      <<<LISTCAP / 256, 256>>>(ew, adw);
    k_spmm1    <<<NN * 32 / 256, 256>>>((const float2*)x);
    k_spmm2_out<<<NN * 32 / 256, 256>>>((const float2*)x, W, bias, (float2*)out);
}